// round 17
// baseline (speedup 1.0000x reference)
#include <cuda_runtime.h>
#include <cuda_fp16.h>

#define BATCH 4
#define CDIM 256
#define NTOK 4096   // 64*64
#define TCD 768     // 3*C
#define FULLMASK 0xffffffffu

// Scratch (allocation-free rule: __device__ globals)
__device__ __half g_xh[BATCH * CDIM * NTOK];   // x converted to fp16, [b][c][n]
__device__ __half g_Q[BATCH * NTOK * CDIM];
__device__ __half g_Kc[BATCH * NTOK * CDIM];   // compacted keys
__device__ __half g_Vc[BATCH * NTOK * CDIM];   // compacted values
__device__ __half g_AOh[BATCH * NTOK * CDIM];
__device__ __half g_Wh[TCD * CDIM];
__device__ __half g_Wph[CDIM * CDIM];
__device__ int    g_pos[BATCH * NTOK];         // scatter index or -1
__device__ int    g_cnt[BATCH];

__device__ __forceinline__ void mma_f16(float d[4], const unsigned a[4],
                                        unsigned b0, unsigned b1) {
    asm volatile(
        "mma.sync.aligned.m16n8k16.row.col.f32.f16.f16.f32 "
        "{%0,%1,%2,%3}, {%4,%5,%6,%7}, {%8,%9}, {%0,%1,%2,%3};\n"
        : "+f"(d[0]), "+f"(d[1]), "+f"(d[2]), "+f"(d[3])
        : "r"(a[0]), "r"(a[1]), "r"(a[2]), "r"(a[3]), "r"(b0), "r"(b1));
}
__device__ __forceinline__ unsigned h2u(__half2 h) { return *(unsigned*)&h; }
__device__ __forceinline__ __half2 u2h(unsigned u) { return *(__half2*)&u; }
__device__ __forceinline__ unsigned ex2h2(unsigned a) {
    unsigned r;
    asm("ex2.approx.f16x2 %0, %1;" : "=r"(r) : "r"(a));
    return r;
}
__device__ __forceinline__ unsigned s2u(const void* p) {
    unsigned u;
    asm("{ .reg .u64 t; cvta.to.shared.u64 t, %1; cvt.u32.u64 %0, t; }"
        : "=r"(u) : "l"(p));
    return u;
}
__device__ __forceinline__ void ldsm_x4(unsigned r[4], unsigned addr) {
    asm volatile("ldmatrix.sync.aligned.m8n8.x4.shared.b16 {%0,%1,%2,%3}, [%4];"
        : "=r"(r[0]), "=r"(r[1]), "=r"(r[2]), "=r"(r[3]) : "r"(addr));
}
__device__ __forceinline__ void ldsm_x4_t(unsigned r[4], unsigned addr) {
    asm volatile("ldmatrix.sync.aligned.m8n8.x4.trans.shared.b16 {%0,%1,%2,%3}, [%4];"
        : "=r"(r[0]), "=r"(r[1]), "=r"(r[2]), "=r"(r[3]) : "r"(addr));
}
__device__ __forceinline__ void cp16(unsigned dst, const void* src) {
    asm volatile("cp.async.cg.shared.global [%0], [%1], 16;" :: "r"(dst), "l"(src));
}
#define CP_COMMIT() asm volatile("cp.async.commit_group;" ::: "memory")
#define CP_WAIT(n)  asm volatile("cp.async.wait_group %0;" :: "n"(n) : "memory")

// ---------------------------------------------------------------------------
// Kernel 0: one-time fp32 -> fp16 conversion: x, Wqkv, Wp.
// ---------------------------------------------------------------------------
#define N_X4_X  (BATCH * CDIM * NTOK / 4)
#define N_X4_W  (TCD * CDIM / 4)
#define N_X4_WP (CDIM * CDIM / 4)

__global__ __launch_bounds__(256) void conv_kernel(const float* __restrict__ x,
                                                   const float* __restrict__ Wqkv,
                                                   const float* __restrict__ Wp) {
    const int idx = blockIdx.x * 256 + threadIdx.x;
    const float4* src;
    uint2* dst;
    int off;
    if (idx < N_X4_X) { src = (const float4*)x; dst = (uint2*)g_xh; off = idx; }
    else if (idx < N_X4_X + N_X4_W) {
        src = (const float4*)Wqkv; dst = (uint2*)g_Wh; off = idx - N_X4_X;
    } else {
        src = (const float4*)Wp; dst = (uint2*)g_Wph; off = idx - N_X4_X - N_X4_W;
    }
    float4 v = src[off];
    uint2 wv;
    wv.x = h2u(__floats2half2_rn(v.x, v.y));
    wv.y = h2u(__floats2half2_rn(v.z, v.w));
    dst[off] = wv;
}

// ---------------------------------------------------------------------------
// Kernel 0b: mask compaction + zero-pad tail of Kc/Vc to 64-multiple.
// ---------------------------------------------------------------------------
__global__ __launch_bounds__(256) void compact_kernel(const int* __restrict__ fg) {
    __shared__ int ps[256];
    const int b = blockIdx.x, tid = threadIdx.x;
    const int* f = fg + b * NTOK + tid * 16;
    int loc[16], c = 0;
#pragma unroll
    for (int i = 0; i < 16; i++) { loc[i] = (f[i] != 0); c += loc[i]; }
    ps[tid] = c;
    __syncthreads();
    for (int s = 1; s < 256; s <<= 1) {
        int v = (tid >= s) ? ps[tid - s] : 0;
        __syncthreads();
        ps[tid] += v;
        __syncthreads();
    }
    int off = ps[tid] - c;
#pragma unroll
    for (int i = 0; i < 16; i++) {
        g_pos[b * NTOK + tid * 16 + i] = loc[i] ? off : -1;
        off += loc[i];
    }
    if (tid == 255) g_cnt[b] = ps[255];
    __syncthreads();
    const int cnt = ps[255];
    const int padded = (cnt + 63) & ~63;
    const int n4 = (padded - cnt) * 32;
    for (int i = tid; i < n4; i += 256) {
        const int row = cnt + (i >> 5), j = i & 31;
        const long o = ((long)b * NTOK + row) * CDIM + j * 8;
        *(uint4*)&g_Kc[o] = make_uint4(0, 0, 0, 0);
        *(uint4*)&g_Vc[o] = make_uint4(0, 0, 0, 0);
    }
}

// ---------------------------------------------------------------------------
// Kernel 1: QKV GEMM (R16 version verbatim).
// ---------------------------------------------------------------------------
#define XQS 36
#define WQS 132
#define QKV_SMEM ((256 * XQS + 128 * WQS) * 4)

__global__ __launch_bounds__(256) void qkv_kernel() {
    extern __shared__ unsigned sqw[];
    unsigned* Xw = sqw;
    unsigned* Wh = sqw + 256 * XQS;

    const int b  = blockIdx.z;
    const int n0 = blockIdx.x * 64;
    const int d0 = blockIdx.y * 128;
    const int tid = threadIdx.x;
    const int lane = tid & 31, w = tid >> 5;
    const int g = lane >> 2, t = lane & 3;
    const int wmd = w >> 2, wnn = w & 3;

    const unsigned whB = s2u(Wh), xwB = s2u(Xw);

#pragma unroll
    for (int tl = 0; tl < 16; tl++) {
        const int u = tid + tl * 256;
        const int d = u >> 5, ch = u & 31;
        cp16(whB + ((d * WQS + ch * 4) << 2), &g_Wh[(long)(d0 + d) * CDIM + ch * 8]);
    }
#pragma unroll
    for (int tl = 0; tl < 8; tl++) {
        const int u = tid + tl * 256;
        const int c = u >> 3, j = u & 7;
        cp16(xwB + ((c * XQS + j * 4) << 2),
             &g_xh[((long)b * CDIM + c) * NTOK + n0 + j * 8]);
    }
    CP_COMMIT();
    CP_WAIT(0);
    __syncthreads();

    const unsigned aB = whB + (((wmd * 64 + (lane & 15)) * WQS + 4 * (lane >> 4)) << 2);
    const unsigned xB = xwB + (((lane & 15) * XQS) << 2) +
                        ((wnn * 16 + (lane >> 4) * 8) << 1);

    float acc[4][2][4] = {};
#pragma unroll
    for (int ks = 0; ks < 16; ks++) {
        unsigned a[4][4];
#pragma unroll
        for (int mt = 0; mt < 4; mt++)
            ldsm_x4(a[mt], aB + ((mt * 16 * WQS + ks * 8) << 2));
        unsigned bb[4];
        ldsm_x4_t(bb, xB + ((ks * 16 * XQS) << 2));
#pragma unroll
        for (int mt = 0; mt < 4; mt++) {
            mma_f16(acc[mt][0], a[mt], bb[0], bb[1]);
            mma_f16(acc[mt][1], a[mt], bb[2], bb[3]);
        }
    }
    __syncthreads();

    __half* Csh = (__half*)sqw;   // [64 n][136 halves]
#pragma unroll
    for (int mt = 0; mt < 4; mt++) {
        const int r0 = wmd * 64 + mt * 16 + g;
#pragma unroll
        for (int nt = 0; nt < 2; nt++) {
            const int col = wnn * 16 + nt * 8 + 2 * t;
            Csh[col * 136 + r0]           = __float2half(acc[mt][nt][0]);
            Csh[(col + 1) * 136 + r0]     = __float2half(acc[mt][nt][1]);
            Csh[col * 136 + r0 + 8]       = __float2half(acc[mt][nt][2]);
            Csh[(col + 1) * 136 + r0 + 8] = __float2half(acc[mt][nt][3]);
        }
    }
    __syncthreads();

    const int seg = d0 >> 8;
    const int dl0 = d0 & 255;
    if (seg == 0) {
#pragma unroll
        for (int tl = 0; tl < 4; tl++) {
            const int u = tid + tl * 256;
            const int n = u >> 4, d8 = u & 15;
            uint4 v = *(const uint4*)&Csh[n * 136 + d8 * 8];
            *(uint4*)&g_Q[((long)b * NTOK + n0 + n) * CDIM + dl0 + d8 * 8] = v;
        }
    } else {
        __half* basec = (seg == 1) ? g_Kc : g_Vc;
#pragma unroll
        for (int tl = 0; tl < 4; tl++) {
            const int u = tid + tl * 256;
            const int n = u >> 4, d8 = u & 15;
            const int np = g_pos[b * NTOK + n0 + n];
            if (np >= 0) {
                uint4 v = *(const uint4*)&Csh[n * 136 + d8 * 8];
                *(uint4*)&basec[((long)b * NTOK + np) * CDIM + dl0 + d8 * 8] = v;
            }
        }
    }
}

// ---------------------------------------------------------------------------
// Kernel 2: fp16 mma flash attention, 64-query CTAs, 64-key tiles,
// 2 CTAs/SM (smem 77.7KB). f16x2 exp softmax. grid (64, 4).
// ---------------------------------------------------------------------------
#define QW2 132
#define PW2 36
#define ATTN_SMEM ((64 * QW2 * 2 + 64 * PW2 + 32 + 128 + 64) * 4)

__global__ __launch_bounds__(256, 2) void attn_kernel() {
    extern __shared__ unsigned smw[];
    unsigned* Qw  = smw;                     // [64][132]
    unsigned* Kw  = Qw + 64 * QW2;           // [64][132] K tile then V tile
    unsigned* Pw  = Kw + 64 * QW2;           // [64][36]
    unsigned* fgh = Pw + 64 * PW2;           // [32] half2 mask pairs
    float* lsumP  = (float*)(fgh + 32);      // [2][64]
    float* runl   = lsumP + 128;             // [64]

    const int b   = blockIdx.y;
    const int q0  = blockIdx.x * 64;
    const int tid = threadIdx.x;
    const int lane = tid & 31, w = tid >> 5;
    const int g = lane >> 2, t = lane & 3;
    const int wmS = w >> 1, wnS = w & 1;     // S: 4m x 2n grid, warp tile 16q x 32k
    const int wmO = w >> 2, wnO = w & 3;     // O: 2m x 4n grid, warp tile 32q x 64c

    const int cnt = g_cnt[b];
    const int padded = (cnt + 63) & ~63;

    const __half* Qg = g_Q + ((long)b * NTOK + q0) * CDIM;
    const __half* Kg = g_Kc + (long)b * NTOK * CDIM;
    const __half* Vg = g_Vc + (long)b * NTOK * CDIM;

    // stage resident Q tile: 64 rows x 256 halves
#pragma unroll
    for (int tl = 0; tl < 8; tl++) {
        const int u = tid + tl * 256;
        const int row = u >> 5, j = u & 31;
        uint4 v = *(const uint4*)&Qg[(long)row * CDIM + j * 8];
        *(uint4*)&Qw[row * QW2 + j * 4] = v;
    }
    if (tid < 64) runl[tid] = 0.0f;

    const unsigned kwB = s2u(Kw);
    const unsigned qaB = s2u(Qw) +
        (((wmS * 16 + (lane & 15)) * QW2 + 4 * (lane >> 4)) << 2);
    const unsigned kbB = kwB +
        (((wnS * 32 + ((lane >> 4) << 3) + (lane & 7)) * QW2 + ((lane >> 3) & 1) * 4) << 2);
    const unsigned paB = s2u(Pw) +
        (((wmO * 32 + (lane & 15)) * PW2 + 4 * (lane >> 4)) << 2);
    const unsigned vbB = kwB + (((lane & 15) * QW2) << 2) +
        ((wnO * 64 + (lane >> 4) * 8) << 1);

    float oacc[2][8][4];
#pragma unroll
    for (int i = 0; i < 2; i++)
#pragma unroll
        for (int j = 0; j < 8; j++)
#pragma unroll
            for (int k = 0; k < 4; k++) oacc[i][j][k] = 0.0f;

    const float SC = 0.0625f * 1.4426950408889634f;

    for (int m0 = 0; m0 < padded; m0 += 64) {
        __syncthreads();   // prev PV done reading Kw; Q/runl visible on tile 0

        // stage K tile (64 keys x 256 halves)
#pragma unroll
        for (int tl = 0; tl < 8; tl++) {
            const int u = tid + tl * 256;
            const int row = u >> 5, j = u & 31;
            cp16(kwB + ((row * QW2 + j * 4) << 2),
                 &Kg[(long)(m0 + row) * CDIM + j * 8]);
        }
        CP_COMMIT();

        if (tid < 32) {
            const float f0 = (m0 + 2 * tid < cnt) ? 1.0f : 0.0f;
            const float f1 = (m0 + 2 * tid + 1 < cnt) ? 1.0f : 0.0f;
            fgh[tid] = h2u(__floats2half2_rn(f0, f1));
        }

        CP_WAIT(0);
        __syncthreads();

        // ---- S = Q K^T: 16 c-steps of 16 ----
        float sacc[4][4] = {};
#pragma unroll
        for (int ks = 0; ks < 16; ks++) {
            unsigned a[4];
            ldsm_x4(a, qaB + ((ks * 8) << 2));
#pragma unroll
            for (int ntp = 0; ntp < 2; ntp++) {
                unsigned bb[4];
                ldsm_x4(bb, kbB + ((ntp * 16 * QW2 + ks * 8) << 2));
                mma_f16(sacc[2 * ntp], a, bb[0], bb[1]);
                mma_f16(sacc[2 * ntp + 1], a, bb[2], bb[3]);
            }
        }
        __syncthreads();   // all warps done reading K

        // stage V tile (same buffer)
#pragma unroll
        for (int tl = 0; tl < 8; tl++) {
            const int u = tid + tl * 256;
            const int row = u >> 5, j = u & 31;
            cp16(kwB + ((row * QW2 + j * 4) << 2),
                 &Vg[(long)(m0 + row) * CDIM + j * 8]);
        }
        CP_COMMIT();

        // ---- softmax via f16x2 exp; P fp16; fp32 row sums ----
        float rs0 = 0.0f, rs1 = 0.0f;
        const int r0 = wmS * 16 + g;
#pragma unroll
        for (int nt = 0; nt < 4; nt++) {
            const int word = wnS * 16 + nt * 4 + t;
            const unsigned mw = fgh[word];
            unsigned e01 = ex2h2(h2u(__floats2half2_rn(sacc[nt][0] * SC, sacc[nt][1] * SC)));
            unsigned e23 = ex2h2(h2u(__floats2half2_rn(sacc[nt][2] * SC, sacc[nt][3] * SC)));
            __half2 p01 = __hmul2(u2h(e01), u2h(mw));
            __half2 p23 = __hmul2(u2h(e23), u2h(mw));
            Pw[r0 * PW2 + word] = h2u(p01);
            Pw[(r0 + 8) * PW2 + word] = h2u(p23);
            float2 f01 = __half22float2(p01);
            float2 f23 = __half22float2(p23);
            rs0 += f01.x + f01.y;
            rs1 += f23.x + f23.y;
        }
        rs0 += __shfl_xor_sync(FULLMASK, rs0, 1);
        rs0 += __shfl_xor_sync(FULLMASK, rs0, 2);
        rs1 += __shfl_xor_sync(FULLMASK, rs1, 1);
        rs1 += __shfl_xor_sync(FULLMASK, rs1, 2);
        if (t == 0) {
            lsumP[wnS * 64 + r0] = rs0;
            lsumP[wnS * 64 + r0 + 8] = rs1;
        }
        CP_WAIT(0);        // V landed
        __syncthreads();   // V + Pw + lsumP visible
        if (tid < 64) runl[tid] += lsumP[tid] + lsumP[64 + tid];

        // ---- O += P V: 4 key-steps of 16; V frags via trans ----
#pragma unroll
        for (int ks = 0; ks < 4; ks++) {
            unsigned a[2][4];
#pragma unroll
            for (int mt = 0; mt < 2; mt++)
                ldsm_x4(a[mt], paB + ((mt * 16 * PW2 + ks * 8) << 2));
#pragma unroll
            for (int ntp = 0; ntp < 4; ntp++) {
                unsigned vv[4];
                ldsm_x4_t(vv, vbB + ((ks * 16 * QW2) << 2) + (ntp << 5));
#pragma unroll
                for (int mt = 0; mt < 2; mt++) {
                    mma_f16(oacc[mt][2 * ntp], a[mt], vv[0], vv[1]);
                    mma_f16(oacc[mt][2 * ntp + 1], a[mt], vv[2], vv[3]);
                }
            }
        }
    }

    // ---- epilogue: normalize and store fp16 AO ----
    __syncthreads();
    __half* AOg = g_AOh + ((long)b * NTOK + q0) * CDIM;
#pragma unroll
    for (int mt = 0; mt < 2; mt++) {
        const int r0 = wmO * 32 + mt * 16 + g;
        const float inv0 = 1.0f / runl[r0];
        const float inv1 = 1.0f / runl[r0 + 8];
#pragma unroll
        for (int nt = 0; nt < 8; nt++) {
            const int col = wnO * 64 + nt * 8 + 2 * t;
            *(__half2*)&AOg[(long)r0 * CDIM + col] =
                __floats2half2_rn(oacc[mt][nt][0] * inv0, oacc[mt][nt][1] * inv0);
            *(__half2*)&AOg[(long)(r0 + 8) * CDIM + col] =
                __floats2half2_rn(oacc[mt][nt][2] * inv1, oacc[mt][nt][3] * inv1);
        }
    }
}

// ---------------------------------------------------------------------------
// Kernel 3: projection (R12 version verbatim — 17.5us).
// ---------------------------------------------------------------------------
#define PJS 132
#define PROJ_SMEM ((128 * PJS + 128 * PJS) * 4)

__global__ __launch_bounds__(256) void proj_kernel(const float* __restrict__ bp,
                                                   float* __restrict__ out) {
    extern __shared__ unsigned spw[];
    unsigned* Ah = spw;
    unsigned* Wh = spw + 128 * PJS;
    float* Cs = (float*)spw;

    const int b   = blockIdx.z;
    const int n0  = blockIdx.x * 128;
    const int co0 = blockIdx.y * 128;
    const int tid = threadIdx.x;
    const int lane = tid & 31, w = tid >> 5;
    const int g = lane >> 2, t = lane & 3;
    const int wm = w >> 1, wn = w & 1;

    const unsigned ahB = s2u(Ah), whB = s2u(Wh);
#pragma unroll
    for (int tl = 0; tl < 16; tl++) {
        const int u = tid + tl * 256;
        const int n = u >> 5, ch = u & 31;
        cp16(ahB + ((n * PJS + ch * 4) << 2),
             &g_AOh[((long)b * NTOK + n0 + n) * CDIM + ch * 8]);
    }
#pragma unroll
    for (int tl = 0; tl < 16; tl++) {
        const int u = tid + tl * 256;
        const int d = u >> 5, ch = u & 31;
        cp16(whB + ((d * PJS + ch * 4) << 2),
             &g_Wph[(long)(co0 + d) * CDIM + ch * 8]);
    }
    CP_COMMIT();
    CP_WAIT(0);
    __syncthreads();

    const unsigned aB = ahB + (((wm * 32 + (lane & 15)) * PJS + 4 * (lane >> 4)) << 2);
    const unsigned bB = whB +
        (((wn * 64 + ((lane >> 4) << 3) + (lane & 7)) * PJS + ((lane >> 3) & 1) * 4) << 2);

    float sacc[2][8][4] = {};
#pragma unroll
    for (int ks = 0; ks < 16; ks++) {
        unsigned a[2][4];
        ldsm_x4(a[0], aB + ((ks * 8) << 2));
        ldsm_x4(a[1], aB + ((16 * PJS + ks * 8) << 2));
#pragma unroll
        for (int ntp = 0; ntp < 4; ntp++) {
            unsigned bb[4];
            ldsm_x4(bb, bB + ((ntp * 16 * PJS + ks * 8) << 2));
            mma_f16(sacc[0][2 * ntp], a[0], bb[0], bb[1]);
            mma_f16(sacc[1][2 * ntp], a[1], bb[0], bb[1]);
            mma_f16(sacc[0][2 * ntp + 1], a[0], bb[2], bb[3]);
            mma_f16(sacc[1][2 * ntp + 1], a[1], bb[2], bb[3]);
        }
    }
    __syncthreads();

#pragma unroll
    for (int mt = 0; mt < 2; mt++) {
        const int r0 = wm * 32 + mt * 16 + g;
#pragma unroll
        for (int nt = 0; nt < 8; nt++) {
            const int col = wn * 64 + nt * 8 + 2 * t;
            Cs[col * PJS + r0]           = sacc[mt][nt][0];
            Cs[(col + 1) * PJS + r0]     = sacc[mt][nt][1];
            Cs[col * PJS + r0 + 8]       = sacc[mt][nt][2];
            Cs[(col + 1) * PJS + r0 + 8] = sacc[mt][nt][3];
        }
    }
    __syncthreads();

#pragma unroll
    for (int tl = 0; tl < 16; tl++) {
        const int u = tid + tl * 256;
        const int d = u >> 5, q = u & 31;
        const float bias = bp[co0 + d];
        float4 v = *(const float4*)&Cs[d * PJS + 4 * q];
        v.x += bias; v.y += bias; v.z += bias; v.w += bias;
        *(float4*)&out[((long)b * CDIM + co0 + d) * NTOK + n0 + 4 * q] = v;
    }
}

// ---------------------------------------------------------------------------
extern "C" void kernel_launch(void* const* d_in, const int* in_sizes, int n_in,
                              void* d_out, int out_size) {
    const float* x    = (const float*)d_in[0];
    const int*   fg   = (const int*)d_in[1];
    const float* Wqkv = (const float*)d_in[2];
    const float* Wp   = (const float*)d_in[3];
    const float* bp   = (const float*)d_in[4];
    float* out = (float*)d_out;

    cudaFuncSetAttribute(qkv_kernel, cudaFuncAttributeMaxDynamicSharedMemorySize, QKV_SMEM);
    cudaFuncSetAttribute(attn_kernel, cudaFuncAttributeMaxDynamicSharedMemorySize, ATTN_SMEM);
    cudaFuncSetAttribute(proj_kernel, cudaFuncAttributeMaxDynamicSharedMemorySize, PROJ_SMEM);

    conv_kernel<<<(N_X4_X + N_X4_W + N_X4_WP) / 256, 256>>>(x, Wqkv, Wp);
    compact_kernel<<<BATCH, 256>>>(fg);
    qkv_kernel<<<dim3(NTOK / 64, TCD / 128, BATCH), 256, QKV_SMEM>>>();
    attn_kernel<<<dim3(NTOK / 64, BATCH), 256, ATTN_SMEM>>>();
    proj_kernel<<<dim3(NTOK / 128, CDIM / 128, BATCH), 256, PROJ_SMEM>>>(bp, out);
}